// round 2
// baseline (speedup 1.0000x reference)
#include <cuda_runtime.h>
#include <cstdint>

#define N_NODES 100000
#define N_EDGES 1600000
#define FEAT    64
#define NGRAPH  512
#define NCLASS  2

// ---------------- scratch (static device globals; no runtime alloc) --------
__device__ __align__(16) float g_agg[N_NODES * FEAT];   // x + sum_{j->i} x_j
__device__ __align__(16) float g_h[N_NODES * FEAT];     // MLP hidden / output
__device__ float    g_gate[N_NODES];
__device__ unsigned g_gmax[NGRAPH];          // ordered-uint encoded max gate
__device__ float    g_denom[NGRAPH];         // sum exp
__device__ __align__(16) float g_praw[NGRAPH * FEAT];   // sum exp * h

// ordered float<->uint encoding for atomicMax on floats of any sign
__device__ __forceinline__ unsigned fenc(float f) {
    unsigned u = __float_as_uint(f);
    return (u & 0x80000000u) ? ~u : (u | 0x80000000u);
}
__device__ __forceinline__ float fdec(unsigned u) {
    return (u & 0x80000000u) ? __uint_as_float(u & 0x7fffffffu)
                             : __uint_as_float(~u);
}

__device__ __forceinline__ void red_add_v4(float* p, float a, float b, float c, float d) {
    asm volatile("red.global.add.v4.f32 [%0], {%1,%2,%3,%4};"
                 :: "l"(p), "f"(a), "f"(b), "f"(c), "f"(d) : "memory");
}

// ---------------- K0a: agg = x --------------------------------------------
__global__ void k_copy_x(const float* __restrict__ x) {
    int idx = blockIdx.x * blockDim.x + threadIdx.x;           // float4 index
    if (idx < N_NODES * FEAT / 4)
        reinterpret_cast<float4*>(g_agg)[idx] =
            reinterpret_cast<const float4*>(x)[idx];
}

// ---------------- K0b: zero pooling buffers --------------------------------
__global__ void k_init_pool() {
    int idx = blockIdx.x * blockDim.x + threadIdx.x;
    if (idx < NGRAPH) { g_gmax[idx] = 0u; g_denom[idx] = 0.0f; }
    if (idx < NGRAPH * FEAT) g_praw[idx] = 0.0f;
}

// ---------------- K1: edge scatter agg[dst] += x[src] ----------------------
// 16 threads per edge, each owns one float4 chunk (coalesced gather).
__global__ void k_scatter(const float* __restrict__ x,
                          const int* __restrict__ ei) {
    long long t = (long long)blockIdx.x * blockDim.x + threadIdx.x;
    if (t >= (long long)N_EDGES * 16) return;
    int e = (int)(t >> 4);
    int c = (int)(t & 15);
    int s = ei[e];
    int d = ei[N_EDGES + e];
    float4 v = __ldg(reinterpret_cast<const float4*>(x + (size_t)s * 64 + c * 4));
    red_add_v4(g_agg + (size_t)d * 64 + c * 4, v.x, v.y, v.z, v.w);
}

// ---------------- K2: per-node 64x64 dense layer (+ optional gate) ---------
// layer==0: in=g_agg, out=g_h (W1,b1).  layer==1: in=g_h, out=g_h (W2,b2)
// and also computes gate + atomicMax into g_gmax.
__global__ __launch_bounds__(128, 3)
void k_mlp(const float* __restrict__ W, const float* __restrict__ b,
           const float* __restrict__ Wg, const float* __restrict__ bg,
           const int* __restrict__ batch, int layer) {
    __shared__ float sW[64 * 64];        // 16 KB, [k][o]
    __shared__ float sX[64 * 128];       // 32 KB, transposed: sX[k*128 + tid]

    int tid = threadIdx.x;
    int i = blockIdx.x * 128 + tid;

    // cooperative broadcast-friendly weight load
    {
        const float4* Wv = reinterpret_cast<const float4*>(W);
        float4* sWv = reinterpret_cast<float4*>(sW);
#pragma unroll
        for (int j = 0; j < 8; j++) sWv[tid + j * 128] = Wv[tid + j * 128];
    }
    __syncthreads();

    if (i >= N_NODES) return;

    const float* in = (layer == 0) ? g_agg : g_h;
    const float* row = in + (size_t)i * FEAT;
    // stage this thread's row transposed into shared (conflict-free reads later)
#pragma unroll
    for (int j = 0; j < 16; j++) {
        float4 v = __ldg(reinterpret_cast<const float4*>(row + 4 * j));
        sX[(4 * j + 0) * 128 + tid] = v.x;
        sX[(4 * j + 1) * 128 + tid] = v.y;
        sX[(4 * j + 2) * 128 + tid] = v.z;
        sX[(4 * j + 3) * 128 + tid] = v.w;
    }

    float acc[64];
#pragma unroll
    for (int j = 0; j < 16; j++) {
        float4 bv = *reinterpret_cast<const float4*>(b + 4 * j);
        acc[4 * j + 0] = bv.x; acc[4 * j + 1] = bv.y;
        acc[4 * j + 2] = bv.z; acc[4 * j + 3] = bv.w;
    }

#pragma unroll 8
    for (int k = 0; k < 64; k++) {
        float xk = sX[k * 128 + tid];
#pragma unroll
        for (int j = 0; j < 16; j++) {
            float4 w = *reinterpret_cast<const float4*>(sW + k * 64 + 4 * j);
            acc[4 * j + 0] = fmaf(xk, w.x, acc[4 * j + 0]);
            acc[4 * j + 1] = fmaf(xk, w.y, acc[4 * j + 1]);
            acc[4 * j + 2] = fmaf(xk, w.z, acc[4 * j + 2]);
            acc[4 * j + 3] = fmaf(xk, w.w, acc[4 * j + 3]);
        }
    }

#pragma unroll
    for (int o = 0; o < 64; o++) acc[o] = fmaxf(acc[o], 0.0f);

    if (layer == 1) {
        float gate = bg[0];
#pragma unroll
        for (int o = 0; o < 64; o++) gate = fmaf(acc[o], __ldg(Wg + o), gate);
        g_gate[i] = gate;
        int bb = batch[i];
        atomicMax(&g_gmax[bb], fenc(gate));
    }

    float* orow = g_h + (size_t)i * FEAT;
#pragma unroll
    for (int j = 0; j < 16; j++) {
        float4 v;
        v.x = acc[4 * j + 0]; v.y = acc[4 * j + 1];
        v.z = acc[4 * j + 2]; v.w = acc[4 * j + 3];
        *reinterpret_cast<float4*>(orow + 4 * j) = v;
    }
}

// ---------------- K3: ex = exp(gate - max); accumulate denom & ex*h --------
__global__ void k_pool(const int* __restrict__ batch) {
    long long t = (long long)blockIdx.x * blockDim.x + threadIdx.x;
    if (t >= (long long)N_NODES * 16) return;
    int i = (int)(t >> 4);
    int c = (int)(t & 15);
    int b = batch[i];
    float m = fdec(g_gmax[b]);
    float ex = expf(g_gate[i] - m);
    if (c == 0) atomicAdd(&g_denom[b], ex);
    float4 hv = *reinterpret_cast<const float4*>(g_h + (size_t)i * 64 + c * 4);
    red_add_v4(g_praw + (size_t)b * 64 + c * 4, ex * hv.x, ex * hv.y, ex * hv.z, ex * hv.w);
}

// ---------------- K4: BN (eval) + linear + log_softmax ---------------------
__global__ void k_final(const float* __restrict__ gamma, const float* __restrict__ beta,
                        const float* __restrict__ mean, const float* __restrict__ var,
                        const float* __restrict__ Wl, const float* __restrict__ bl,
                        float* __restrict__ out) {
    int g = blockIdx.x * blockDim.x + threadIdx.x;
    if (g >= NGRAPH) return;
    float d = g_denom[g];
    float inv = d > 0.0f ? 1.0f / d : 0.0f;
    float l0 = bl[0], l1 = bl[1];
#pragma unroll 8
    for (int f = 0; f < FEAT; f++) {
        float p = g_praw[g * FEAT + f] * inv;
        float nrm = (p - mean[f]) * rsqrtf(var[f] + 1e-5f) * gamma[f] + beta[f];
        l0 = fmaf(nrm, Wl[f * 2 + 0], l0);
        l1 = fmaf(nrm, Wl[f * 2 + 1], l1);
    }
    float m = fmaxf(l0, l1);
    float lse = m + logf(expf(l0 - m) + expf(l1 - m));
    out[g * 2 + 0] = l0 - lse;
    out[g * 2 + 1] = l1 - lse;
}

// ---------------- launch ----------------------------------------------------
extern "C" void kernel_launch(void* const* d_in, const int* in_sizes, int n_in,
                              void* d_out, int out_size) {
    const float* x     = (const float*)d_in[0];
    const int*   ei    = (const int*)d_in[1];
    const int*   batch = (const int*)d_in[2];
    const float* W1 = (const float*)d_in[3];
    const float* b1 = (const float*)d_in[4];
    const float* W2 = (const float*)d_in[5];
    const float* b2 = (const float*)d_in[6];
    const float* Wg = (const float*)d_in[7];
    const float* bg = (const float*)d_in[8];
    const float* bn_gamma = (const float*)d_in[9];
    const float* bn_beta  = (const float*)d_in[10];
    const float* bn_mean  = (const float*)d_in[11];
    const float* bn_var   = (const float*)d_in[12];
    const float* W_lin = (const float*)d_in[13];
    const float* b_lin = (const float*)d_in[14];
    float* out = (float*)d_out;

    k_copy_x<<<(N_NODES * FEAT / 4 + 255) / 256, 256>>>(x);
    k_init_pool<<<(NGRAPH * FEAT + 255) / 256, 256>>>();
    k_scatter<<<(int)(((long long)N_EDGES * 16 + 255) / 256), 256>>>(x, ei);
    k_mlp<<<(N_NODES + 127) / 128, 128>>>(W1, b1, Wg, bg, batch, 0);
    k_mlp<<<(N_NODES + 127) / 128, 128>>>(W2, b2, Wg, bg, batch, 1);
    k_pool<<<(int)(((long long)N_NODES * 16 + 255) / 256), 256>>>(batch);
    k_final<<<(NGRAPH + 255) / 256, 256>>>(bn_gamma, bn_beta, bn_mean, bn_var,
                                           W_lin, b_lin, out);
}

// round 3
// speedup vs baseline: 1.1693x; 1.1693x over previous
#include <cuda_runtime.h>
#include <cstdint>

#define N_NODES 100000
#define N_EDGES 1600000
#define FEAT    64
#define NGRAPH  512
#define SCAN_B  1024
#define NB_SCAN ((N_NODES + SCAN_B - 1) / SCAN_B)   // 98

// ---------------- scratch (static device globals) ---------------------------
__device__ __align__(16) float g_agg[N_NODES * FEAT];
__device__ __align__(16) float g_h[N_NODES * FEAT];
__device__ float    g_gate[N_NODES];
__device__ unsigned g_gmax[NGRAPH];
__device__ float    g_denom[NGRAPH];
__device__ __align__(16) float g_praw[NGRAPH * FEAT];

__device__ int g_deg[N_NODES];
__device__ int g_start[N_NODES + 1];
__device__ int g_cursor[N_NODES];
__device__ int g_adj[N_EDGES];
__device__ int g_bsum[128];
__device__ int g_boff[128];

// ordered float<->uint encoding for atomicMax on floats
__device__ __forceinline__ unsigned fenc(float f) {
    unsigned u = __float_as_uint(f);
    return (u & 0x80000000u) ? ~u : (u | 0x80000000u);
}
__device__ __forceinline__ float fdec(unsigned u) {
    return (u & 0x80000000u) ? __uint_as_float(u & 0x7fffffffu)
                             : __uint_as_float(~u);
}
__device__ __forceinline__ void red_add_v4(float* p, float a, float b, float c, float d) {
    asm volatile("red.global.add.v4.f32 [%0], {%1,%2,%3,%4};"
                 :: "l"(p), "f"(a), "f"(b), "f"(c), "f"(d) : "memory");
}

// ---------------- init ------------------------------------------------------
__global__ void k_init() {
    int idx = blockIdx.x * blockDim.x + threadIdx.x;
    if (idx < NGRAPH) { g_gmax[idx] = 0u; g_denom[idx] = 0.0f; }
    if (idx < NGRAPH * FEAT) g_praw[idx] = 0.0f;
    if (idx < N_NODES) g_deg[idx] = 0;
}

// ---------------- CSR build -------------------------------------------------
__global__ void k_count(const int* __restrict__ ei) {
    int e = blockIdx.x * blockDim.x + threadIdx.x;
    if (e < N_EDGES) atomicAdd(&g_deg[ei[N_EDGES + e]], 1);
}

__global__ void k_scan1() {
    __shared__ int ss[SCAN_B];
    int tid = threadIdx.x;
    int i = blockIdx.x * SCAN_B + tid;
    int v = (i < N_NODES) ? g_deg[i] : 0;
    ss[tid] = v;
    __syncthreads();
    for (int off = 1; off < SCAN_B; off <<= 1) {
        int t2 = (tid >= off) ? ss[tid - off] : 0;
        __syncthreads();
        ss[tid] += t2;
        __syncthreads();
    }
    if (i < N_NODES) g_start[i] = ss[tid] - v;      // block-local exclusive
    if (tid == SCAN_B - 1) g_bsum[blockIdx.x] = ss[tid];
}

__global__ void k_scan2() {
    __shared__ int ss[128];
    int tid = threadIdx.x;
    int v = (tid < NB_SCAN) ? g_bsum[tid] : 0;
    ss[tid] = v;
    __syncthreads();
    for (int off = 1; off < 128; off <<= 1) {
        int t2 = (tid >= off) ? ss[tid - off] : 0;
        __syncthreads();
        ss[tid] += t2;
        __syncthreads();
    }
    if (tid < NB_SCAN) g_boff[tid] = ss[tid] - v;
    if (tid == 127) g_start[N_NODES] = ss[127];     // total = E
}

__global__ void k_scan3() {
    int i = blockIdx.x * blockDim.x + threadIdx.x;
    if (i < N_NODES) {
        int s = g_start[i] + g_boff[i >> 10];
        g_start[i] = s;
        g_cursor[i] = s;
    }
}

__global__ void k_fill(const int* __restrict__ ei) {
    int e = blockIdx.x * blockDim.x + threadIdx.x;
    if (e < N_EDGES) {
        int d = ei[N_EDGES + e];
        int pos = atomicAdd(&g_cursor[d], 1);
        g_adj[pos] = ei[e];
    }
}

// ---------------- gather-reduce: agg[i] = x[i] + sum_{j->i} x[j] ------------
// 16 threads per node; adj indices broadcast via shfl within the 16-group.
__global__ void k_gather(const float* __restrict__ x) {
    int t = blockIdx.x * blockDim.x + threadIdx.x;
    int i = t >> 4;
    if (i >= N_NODES) return;
    int c = t & 15;
    unsigned hm = 0xFFFFu << (threadIdx.x & 16);
    int s0 = g_start[i], s1 = g_start[i + 1];
    const float* xp = x + c * 4;
    float4 a = __ldg(reinterpret_cast<const float4*>(x + (size_t)i * 64 + c * 4));
    float ax = a.x, ay = a.y, az = a.z, aw = a.w;
    for (int e = s0; e < s1; e += 4) {
        int na = s1 - e;
        int aj = (c < 4 && c < na) ? g_adj[e + c] : 0;
#pragma unroll
        for (int q = 0; q < 4; q++) {
            int j = __shfl_sync(hm, aj, q, 16);
            if (q < na) {
                float4 v = __ldg(reinterpret_cast<const float4*>(xp + (size_t)j * 64));
                ax += v.x; ay += v.y; az += v.z; aw += v.w;
            }
        }
    }
    *reinterpret_cast<float4*>(g_agg + (size_t)i * 64 + c * 4) =
        make_float4(ax, ay, az, aw);
}

// ---------------- MLP layer: 128-node x 64-out tile, 4x8 micro-tiles --------
__global__ __launch_bounds__(256, 4)
void k_mlp(const float* __restrict__ W, const float* __restrict__ b,
           const float* __restrict__ Wg, const float* __restrict__ bg,
           const int* __restrict__ batch, int layer) {
    __shared__ float sX[64 * 128];   // [k][node], 32 KB
    __shared__ float sW[64 * 64];    // [k][o],    16 KB (reused for gate partials)

    int tid = threadIdx.x;
    int tx = tid & 31, ty = tid >> 5;
    int base = blockIdx.x * 128;
    const float* in = (layer == 0) ? g_agg : g_h;

    // load W (row-major [k][o]) straight in
    {
        const float4* Wv = reinterpret_cast<const float4*>(W);
        float4* sWv = reinterpret_cast<float4*>(sW);
#pragma unroll
        for (int j = 0; j < 4; j++) sWv[tid + j * 256] = Wv[tid + j * 256];
    }
    // load X transposed: 2 threads per node row
    {
        int r = tid >> 1, half = tid & 1;
        int gi = base + r;
        const float* row = in + (size_t)gi * 64 + half * 32;
#pragma unroll
        for (int j = 0; j < 8; j++) {
            float4 v = (gi < N_NODES)
                ? __ldg(reinterpret_cast<const float4*>(row + 4 * j))
                : make_float4(0.f, 0.f, 0.f, 0.f);
            int k0 = half * 32 + 4 * j;
            sX[(k0 + 0) * 128 + r] = v.x;
            sX[(k0 + 1) * 128 + r] = v.y;
            sX[(k0 + 2) * 128 + r] = v.z;
            sX[(k0 + 3) * 128 + r] = v.w;
        }
    }
    __syncthreads();

    float acc[4][8];
    {
        float4 ba = *reinterpret_cast<const float4*>(b + ty * 8);
        float4 bb = *reinterpret_cast<const float4*>(b + ty * 8 + 4);
#pragma unroll
        for (int n = 0; n < 4; n++) {
            acc[n][0] = ba.x; acc[n][1] = ba.y; acc[n][2] = ba.z; acc[n][3] = ba.w;
            acc[n][4] = bb.x; acc[n][5] = bb.y; acc[n][6] = bb.z; acc[n][7] = bb.w;
        }
    }

#pragma unroll 8
    for (int k = 0; k < 64; k++) {
        float4 xv = *reinterpret_cast<const float4*>(&sX[k * 128 + tx * 4]);
        float4 wa = *reinterpret_cast<const float4*>(&sW[k * 64 + ty * 8]);
        float4 wb = *reinterpret_cast<const float4*>(&sW[k * 64 + ty * 8 + 4]);
        float xn[4] = {xv.x, xv.y, xv.z, xv.w};
        float wo[8] = {wa.x, wa.y, wa.z, wa.w, wb.x, wb.y, wb.z, wb.w};
#pragma unroll
        for (int n = 0; n < 4; n++)
#pragma unroll
            for (int o = 0; o < 8; o++)
                acc[n][o] = fmaf(xn[n], wo[o], acc[n][o]);
    }

    // relu + store h
#pragma unroll
    for (int n = 0; n < 4; n++) {
#pragma unroll
        for (int o = 0; o < 8; o++) acc[n][o] = fmaxf(acc[n][o], 0.0f);
        int gi = base + tx * 4 + n;
        if (gi < N_NODES) {
            *reinterpret_cast<float4*>(g_h + (size_t)gi * 64 + ty * 8) =
                make_float4(acc[n][0], acc[n][1], acc[n][2], acc[n][3]);
            *reinterpret_cast<float4*>(g_h + (size_t)gi * 64 + ty * 8 + 4) =
                make_float4(acc[n][4], acc[n][5], acc[n][6], acc[n][7]);
        }
    }

    if (layer == 1) {
        float wg[8];
#pragma unroll
        for (int o = 0; o < 8; o++) wg[o] = __ldg(Wg + ty * 8 + o);
        __syncthreads();              // all warps done reading sW
        float* sG = sW;               // reuse as gate partials [8][128]
#pragma unroll
        for (int n = 0; n < 4; n++) {
            float gp = 0.0f;
#pragma unroll
            for (int o = 0; o < 8; o++) gp = fmaf(acc[n][o], wg[o], gp);
            sG[ty * 128 + tx * 4 + n] = gp;
        }
        __syncthreads();
        if (tid < 128) {
            int gi = base + tid;
            if (gi < N_NODES) {
                float g = bg[0];
#pragma unroll
                for (int q = 0; q < 8; q++) g += sG[q * 128 + tid];
                g_gate[gi] = g;
                atomicMax(&g_gmax[batch[gi]], fenc(g));
            }
        }
    }
}

// ---------------- pool: denom & sum(ex*h) -----------------------------------
__global__ void k_pool(const int* __restrict__ batch) {
    long long t = (long long)blockIdx.x * blockDim.x + threadIdx.x;
    if (t >= (long long)N_NODES * 16) return;
    int i = (int)(t >> 4);
    int c = (int)(t & 15);
    int b = batch[i];
    float m = fdec(g_gmax[b]);
    float ex = expf(g_gate[i] - m);
    if (c == 0) atomicAdd(&g_denom[b], ex);
    float4 hv = *reinterpret_cast<const float4*>(g_h + (size_t)i * 64 + c * 4);
    red_add_v4(g_praw + (size_t)b * 64 + c * 4,
               ex * hv.x, ex * hv.y, ex * hv.z, ex * hv.w);
}

// ---------------- final: BN + linear + log_softmax --------------------------
__global__ void k_final(const float* __restrict__ gamma, const float* __restrict__ beta,
                        const float* __restrict__ mean, const float* __restrict__ var,
                        const float* __restrict__ Wl, const float* __restrict__ bl,
                        float* __restrict__ out) {
    int g = blockIdx.x * blockDim.x + threadIdx.x;
    if (g >= NGRAPH) return;
    float d = g_denom[g];
    float inv = d > 0.0f ? 1.0f / d : 0.0f;
    float l0 = bl[0], l1 = bl[1];
#pragma unroll 8
    for (int f = 0; f < FEAT; f++) {
        float p = g_praw[g * FEAT + f] * inv;
        float nrm = (p - mean[f]) * rsqrtf(var[f] + 1e-5f) * gamma[f] + beta[f];
        l0 = fmaf(nrm, Wl[f * 2 + 0], l0);
        l1 = fmaf(nrm, Wl[f * 2 + 1], l1);
    }
    float m = fmaxf(l0, l1);
    float lse = m + logf(expf(l0 - m) + expf(l1 - m));
    out[g * 2 + 0] = l0 - lse;
    out[g * 2 + 1] = l1 - lse;
}

// ---------------- launch ----------------------------------------------------
extern "C" void kernel_launch(void* const* d_in, const int* in_sizes, int n_in,
                              void* d_out, int out_size) {
    const float* x     = (const float*)d_in[0];
    const int*   ei    = (const int*)d_in[1];
    const int*   batch = (const int*)d_in[2];
    const float* W1 = (const float*)d_in[3];
    const float* b1 = (const float*)d_in[4];
    const float* W2 = (const float*)d_in[5];
    const float* b2 = (const float*)d_in[6];
    const float* Wg = (const float*)d_in[7];
    const float* bg = (const float*)d_in[8];
    const float* bn_gamma = (const float*)d_in[9];
    const float* bn_beta  = (const float*)d_in[10];
    const float* bn_mean  = (const float*)d_in[11];
    const float* bn_var   = (const float*)d_in[12];
    const float* W_lin = (const float*)d_in[13];
    const float* b_lin = (const float*)d_in[14];
    float* out = (float*)d_out;

    k_init<<<(N_NODES + 255) / 256, 256>>>();
    k_count<<<(N_EDGES + 255) / 256, 256>>>(ei);
    k_scan1<<<NB_SCAN, SCAN_B>>>();
    k_scan2<<<1, 128>>>();
    k_scan3<<<(N_NODES + 255) / 256, 256>>>();
    k_fill<<<(N_EDGES + 255) / 256, 256>>>(ei);
    k_gather<<<(N_NODES * 16 + 255) / 256, 256>>>(x);
    k_mlp<<<(N_NODES + 127) / 128, 256>>>(W1, b1, Wg, bg, batch, 0);
    k_mlp<<<(N_NODES + 127) / 128, 256>>>(W2, b2, Wg, bg, batch, 1);
    k_pool<<<(N_NODES * 16 + 255) / 256, 256>>>(batch);
    k_final<<<(NGRAPH + 255) / 256, 256>>>(bn_gamma, bn_beta, bn_mean, bn_var,
                                           W_lin, b_lin, out);
}

// round 4
// speedup vs baseline: 1.2069x; 1.0322x over previous
#include <cuda_runtime.h>
#include <cstdint>

#define N_NODES 100000
#define N_EDGES 1600000
#define FEAT    64
#define NGRAPH  512
#define SCAN_B  1024
#define NB_SCAN ((N_NODES + SCAN_B - 1) / SCAN_B)   // 98

typedef unsigned long long u64;

// ---------------- scratch (static device globals) ---------------------------
__device__ __align__(16) float g_agg[N_NODES * FEAT];
__device__ __align__(16) float g_h[N_NODES * FEAT];
__device__ float    g_gate[N_NODES];
__device__ unsigned g_gmax[NGRAPH];
__device__ float    g_denom[NGRAPH];
__device__ __align__(16) float g_praw[NGRAPH * FEAT];

__device__ int g_deg[N_NODES];
__device__ int g_start[N_NODES + 1];
__device__ int g_cursor[N_NODES];
__device__ int g_adj[N_EDGES];
__device__ int g_bsum[128];

// ---------------- helpers ----------------------------------------------------
__device__ __forceinline__ unsigned fenc(float f) {
    unsigned u = __float_as_uint(f);
    return (u & 0x80000000u) ? ~u : (u | 0x80000000u);
}
__device__ __forceinline__ float fdec(unsigned u) {
    return (u & 0x80000000u) ? __uint_as_float(u & 0x7fffffffu)
                             : __uint_as_float(~u);
}
__device__ __forceinline__ void red_add_v4(float* p, float a, float b, float c, float d) {
    asm volatile("red.global.add.v4.f32 [%0], {%1,%2,%3,%4};"
                 :: "l"(p), "f"(a), "f"(b), "f"(c), "f"(d) : "memory");
}
__device__ __forceinline__ u64 pack2(float a, float b) {
    u64 d; asm("mov.b64 %0, {%1, %2};" : "=l"(d) : "f"(a), "f"(b)); return d;
}
__device__ __forceinline__ void unpack2(u64 v, float& a, float& b) {
    asm("mov.b64 {%0, %1}, %2;" : "=f"(a), "=f"(b) : "l"(v));
}
__device__ __forceinline__ u64 fma2(u64 a, u64 b, u64 c) {
    u64 d; asm("fma.rn.f32x2 %0, %1, %2, %3;" : "=l"(d) : "l"(a), "l"(b), "l"(c));
    return d;
}

// ---------------- init: deg=0, g_start[N]=E ---------------------------------
__global__ void k_init() {
    int idx = blockIdx.x * blockDim.x + threadIdx.x;
    if (idx < N_NODES) g_deg[idx] = 0;
    if (idx == 0) g_start[N_NODES] = N_EDGES;
}

// ---------------- CSR build -------------------------------------------------
__global__ void k_count(const int* __restrict__ ei) {
    int e = blockIdx.x * blockDim.x + threadIdx.x;
    if (e < N_EDGES) atomicAdd(&g_deg[ei[N_EDGES + e]], 1);
}

// block-local exclusive scan + block sums; also zeroes pooling buffers
__global__ void k_scan1() {
    __shared__ int ss[SCAN_B];
    int tid = threadIdx.x;
    int i = blockIdx.x * SCAN_B + tid;
    // fold pool-buffer init here (runs well before mlp2/pool)
    if (i < NGRAPH) { g_gmax[i] = 0u; g_denom[i] = 0.0f; }
    if (i < NGRAPH * FEAT) g_praw[i] = 0.0f;
    int v = (i < N_NODES) ? g_deg[i] : 0;
    ss[tid] = v;
    __syncthreads();
    for (int off = 1; off < SCAN_B; off <<= 1) {
        int t2 = (tid >= off) ? ss[tid - off] : 0;
        __syncthreads();
        ss[tid] += t2;
        __syncthreads();
    }
    if (i < N_NODES) g_start[i] = ss[tid] - v;
    if (tid == SCAN_B - 1) g_bsum[blockIdx.x] = ss[tid];
}

// per-block lookback over g_bsum + finalize start/cursor (replaces scan2+scan3)
__global__ void k_scan3() {
    __shared__ int ss[128];
    __shared__ int sprefix;
    int tid = threadIdx.x;
    int bid = blockIdx.x;
    if (tid < 128) ss[tid] = (tid < bid) ? g_bsum[tid] : 0;
    __syncthreads();
    if (tid < 64) ss[tid] += ss[tid + 64];
    __syncthreads();
    if (tid < 32) {
        int s = ss[tid] + ss[tid + 32];
#pragma unroll
        for (int off = 16; off > 0; off >>= 1)
            s += __shfl_down_sync(0xFFFFFFFFu, s, off);
        if (tid == 0) sprefix = s;
    }
    __syncthreads();
    int i = bid * SCAN_B + tid;
    if (i < N_NODES) {
        int s = g_start[i] + sprefix;
        g_start[i] = s;
        g_cursor[i] = s;
    }
}

__global__ void k_fill(const int* __restrict__ ei) {
    int e = blockIdx.x * blockDim.x + threadIdx.x;
    if (e < N_EDGES) {
        int d = ei[N_EDGES + e];
        int pos = atomicAdd(&g_cursor[d], 1);
        g_adj[pos] = ei[e];
    }
}

// ---------------- gather-reduce: agg[i] = x[i] + sum_{j->i} x[j] ------------
__global__ void k_gather(const float* __restrict__ x) {
    int t = blockIdx.x * blockDim.x + threadIdx.x;
    int i = t >> 4;
    if (i >= N_NODES) return;
    int c = t & 15;
    unsigned hm = 0xFFFFu << (threadIdx.x & 16);
    int s0 = g_start[i], s1 = g_start[i + 1];
    const float* xp = x + c * 4;
    float4 a = __ldg(reinterpret_cast<const float4*>(x + (size_t)i * 64 + c * 4));
    float ax = a.x, ay = a.y, az = a.z, aw = a.w;
    for (int e = s0; e < s1; e += 4) {
        int na = s1 - e;
        int aj = (c < 4 && c < na) ? g_adj[e + c] : 0;
#pragma unroll
        for (int q = 0; q < 4; q++) {
            int j = __shfl_sync(hm, aj, q, 16);
            if (q < na) {
                float4 v = __ldg(reinterpret_cast<const float4*>(xp + (size_t)j * 64));
                ax += v.x; ay += v.y; az += v.z; aw += v.w;
            }
        }
    }
    *reinterpret_cast<float4*>(g_agg + (size_t)i * 64 + c * 4) =
        make_float4(ax, ay, az, aw);
}

// ---------------- MLP layer with packed f32x2 FMA ---------------------------
// 128-node x 64-out tile; thread = 4 nodes x 8 outputs (4 output-pairs).
__global__ __launch_bounds__(256, 3)
void k_mlp(const float* __restrict__ W, const float* __restrict__ b,
           const float* __restrict__ Wg, const float* __restrict__ bg,
           const int* __restrict__ batch, int layer) {
    __shared__ float sX[64 * 128];   // [k][node], 32 KB
    __shared__ float sW[64 * 64];    // [k][o],    16 KB (reused for gate partials)

    int tid = threadIdx.x;
    int tx = tid & 31, ty = tid >> 5;
    int base = blockIdx.x * 128;
    const float* in = (layer == 0) ? g_agg : g_h;

    {
        const float4* Wv = reinterpret_cast<const float4*>(W);
        float4* sWv = reinterpret_cast<float4*>(sW);
#pragma unroll
        for (int j = 0; j < 4; j++) sWv[tid + j * 256] = Wv[tid + j * 256];
    }
    {
        int r = tid >> 1, half = tid & 1;
        int gi = base + r;
        const float* row = in + (size_t)gi * 64 + half * 32;
#pragma unroll
        for (int j = 0; j < 8; j++) {
            float4 v = (gi < N_NODES)
                ? __ldg(reinterpret_cast<const float4*>(row + 4 * j))
                : make_float4(0.f, 0.f, 0.f, 0.f);
            int k0 = half * 32 + 4 * j;
            sX[(k0 + 0) * 128 + r] = v.x;
            sX[(k0 + 1) * 128 + r] = v.y;
            sX[(k0 + 2) * 128 + r] = v.z;
            sX[(k0 + 3) * 128 + r] = v.w;
        }
    }
    __syncthreads();

    // acc[node][output-pair], f32x2 packed
    u64 acc[4][4];
    {
        const u64* bp = reinterpret_cast<const u64*>(b) + ty * 4;
        u64 b0 = __ldg((const unsigned long long*)bp + 0);
        u64 b1 = __ldg((const unsigned long long*)bp + 1);
        u64 b2 = __ldg((const unsigned long long*)bp + 2);
        u64 b3 = __ldg((const unsigned long long*)bp + 3);
#pragma unroll
        for (int n = 0; n < 4; n++) {
            acc[n][0] = b0; acc[n][1] = b1; acc[n][2] = b2; acc[n][3] = b3;
        }
    }

#pragma unroll 8
    for (int k = 0; k < 64; k++) {
        float4 xv = *reinterpret_cast<const float4*>(&sX[k * 128 + tx * 4]);
        // weight pairs: consecutive floats in sW row are ready-made f32x2 pairs
        longlong2 wA = *reinterpret_cast<const longlong2*>(&sW[k * 64 + ty * 8]);
        longlong2 wB = *reinterpret_cast<const longlong2*>(&sW[k * 64 + ty * 8 + 4]);
        u64 wp[4] = {(u64)wA.x, (u64)wA.y, (u64)wB.x, (u64)wB.y};
        u64 xd[4] = {pack2(xv.x, xv.x), pack2(xv.y, xv.y),
                     pack2(xv.z, xv.z), pack2(xv.w, xv.w)};
#pragma unroll
        for (int n = 0; n < 4; n++)
#pragma unroll
            for (int p = 0; p < 4; p++)
                acc[n][p] = fma2(xd[n], wp[p], acc[n][p]);
    }

    // unpack, relu, store h (+ gate partials for layer 1)
    float wg[8];
    if (layer == 1) {
#pragma unroll
        for (int o = 0; o < 8; o++) wg[o] = __ldg(Wg + ty * 8 + o);
        __syncthreads();                 // done reading sW; reuse as gate scratch
    }
    float* sG = sW;                      // [8][128] gate partials

#pragma unroll
    for (int n = 0; n < 4; n++) {
        float o[8];
#pragma unroll
        for (int p = 0; p < 4; p++) unpack2(acc[n][p], o[2 * p], o[2 * p + 1]);
#pragma unroll
        for (int q = 0; q < 8; q++) o[q] = fmaxf(o[q], 0.0f);
        int gi = base + tx * 4 + n;
        if (gi < N_NODES) {
            *reinterpret_cast<float4*>(g_h + (size_t)gi * 64 + ty * 8) =
                make_float4(o[0], o[1], o[2], o[3]);
            *reinterpret_cast<float4*>(g_h + (size_t)gi * 64 + ty * 8 + 4) =
                make_float4(o[4], o[5], o[6], o[7]);
        }
        if (layer == 1) {
            float gp = 0.0f;
#pragma unroll
            for (int q = 0; q < 8; q++) gp = fmaf(o[q], wg[q], gp);
            sG[ty * 128 + tx * 4 + n] = gp;
        }
    }

    if (layer == 1) {
        __syncthreads();
        if (tid < 128) {
            int gi = base + tid;
            if (gi < N_NODES) {
                float g = bg[0];
#pragma unroll
                for (int q = 0; q < 8; q++) g += sG[q * 128 + tid];
                g_gate[gi] = g;
                atomicMax(&g_gmax[batch[gi]], fenc(g));
            }
        }
    }
}

// ---------------- pool: denom & sum(ex*h) -----------------------------------
__global__ void k_pool(const int* __restrict__ batch) {
    long long t = (long long)blockIdx.x * blockDim.x + threadIdx.x;
    if (t >= (long long)N_NODES * 16) return;
    int i = (int)(t >> 4);
    int c = (int)(t & 15);
    int b = batch[i];
    float m = fdec(g_gmax[b]);
    float ex = expf(g_gate[i] - m);
    if (c == 0) atomicAdd(&g_denom[b], ex);
    float4 hv = *reinterpret_cast<const float4*>(g_h + (size_t)i * 64 + c * 4);
    red_add_v4(g_praw + (size_t)b * 64 + c * 4,
               ex * hv.x, ex * hv.y, ex * hv.z, ex * hv.w);
}

// ---------------- final: BN + linear + log_softmax --------------------------
__global__ void k_final(const float* __restrict__ gamma, const float* __restrict__ beta,
                        const float* __restrict__ mean, const float* __restrict__ var,
                        const float* __restrict__ Wl, const float* __restrict__ bl,
                        float* __restrict__ out) {
    int g = blockIdx.x * blockDim.x + threadIdx.x;
    if (g >= NGRAPH) return;
    float d = g_denom[g];
    float inv = d > 0.0f ? 1.0f / d : 0.0f;
    float l0 = bl[0], l1 = bl[1];
#pragma unroll 8
    for (int f = 0; f < FEAT; f++) {
        float p = g_praw[g * FEAT + f] * inv;
        float nrm = (p - mean[f]) * rsqrtf(var[f] + 1e-5f) * gamma[f] + beta[f];
        l0 = fmaf(nrm, Wl[f * 2 + 0], l0);
        l1 = fmaf(nrm, Wl[f * 2 + 1], l1);
    }
    float m = fmaxf(l0, l1);
    float lse = m + logf(expf(l0 - m) + expf(l1 - m));
    out[g * 2 + 0] = l0 - lse;
    out[g * 2 + 1] = l1 - lse;
}

// ---------------- launch ----------------------------------------------------
extern "C" void kernel_launch(void* const* d_in, const int* in_sizes, int n_in,
                              void* d_out, int out_size) {
    const float* x     = (const float*)d_in[0];
    const int*   ei    = (const int*)d_in[1];
    const int*   batch = (const int*)d_in[2];
    const float* W1 = (const float*)d_in[3];
    const float* b1 = (const float*)d_in[4];
    const float* W2 = (const float*)d_in[5];
    const float* b2 = (const float*)d_in[6];
    const float* Wg = (const float*)d_in[7];
    const float* bg = (const float*)d_in[8];
    const float* bn_gamma = (const float*)d_in[9];
    const float* bn_beta  = (const float*)d_in[10];
    const float* bn_mean  = (const float*)d_in[11];
    const float* bn_var   = (const float*)d_in[12];
    const float* W_lin = (const float*)d_in[13];
    const float* b_lin = (const float*)d_in[14];
    float* out = (float*)d_out;

    k_init<<<(N_NODES + 255) / 256, 256>>>();
    k_count<<<(N_EDGES + 255) / 256, 256>>>(ei);
    k_scan1<<<NB_SCAN, SCAN_B>>>();
    k_scan3<<<NB_SCAN, SCAN_B>>>();
    k_fill<<<(N_EDGES + 255) / 256, 256>>>(ei);
    k_gather<<<(N_NODES * 16 + 255) / 256, 256>>>(x);
    k_mlp<<<(N_NODES + 127) / 128, 256>>>(W1, b1, Wg, bg, batch, 0);
    k_mlp<<<(N_NODES + 127) / 128, 256>>>(W2, b2, Wg, bg, batch, 1);
    k_pool<<<(N_NODES * 16 + 255) / 256, 256>>>(batch);
    k_final<<<(NGRAPH + 255) / 256, 256>>>(bn_gamma, bn_beta, bn_mean, bn_var,
                                           W_lin, b_lin, out);
}